// round 10
// baseline (speedup 1.0000x reference)
#include <cuda_runtime.h>
#include <cstdint>

#define B_ 8
#define C_ 384
#define L_ 1024
#define H_ 6
#define D_ 64
#define NW_ 9   // 2*window+1

// Scratch (allocation-free rule: device globals). All [b][l][c] layout.
__device__ float g_qT[B_*L_*C_];
__device__ float g_kT[B_*L_*C_];
__device__ float g_vT[B_*L_*C_];
__device__ float g_xT[B_*L_*C_];
__device__ float g_resT[B_*L_*C_];

__device__ __forceinline__ uint32_t f2tf32(float f) {
    uint32_t r;
    asm("cvt.rna.tf32.f32 %0, %1;" : "=r"(r) : "f"(f));
    return r;
}

__device__ __forceinline__ void mma_tf32(float* d, const uint32_t* a,
                                         uint32_t b0, uint32_t b1) {
    asm volatile("mma.sync.aligned.m16n8k8.row.col.f32.tf32.tf32.f32 "
                 "{%0,%1,%2,%3}, {%4,%5,%6,%7}, {%8,%9}, {%0,%1,%2,%3};"
                 : "+f"(d[0]), "+f"(d[1]), "+f"(d[2]), "+f"(d[3])
                 : "r"(a[0]), "r"(a[1]), "r"(a[2]), "r"(a[3]),
                   "r"(b0), "r"(b1));
}

__device__ __forceinline__ uint32_t smem_u32(const void* p) {
    uint32_t a;
    asm("{ .reg .u64 t; cvta.to.shared.u64 t, %1; cvt.u32.u64 %0, t; }"
        : "=r"(a) : "l"(p));
    return a;
}
__device__ __forceinline__ void cp_async16(uint32_t s, const void* g) {
    asm volatile("cp.async.cg.shared.global [%0], [%1], 16;" :: "r"(s), "l"(g));
}
#define CP_COMMIT() asm volatile("cp.async.commit_group;" ::: "memory")
#define CP_WAIT1()  asm volatile("cp.async.wait_group 1;" ::: "memory")
#define CP_WAIT0()  asm volatile("cp.async.wait_group 0;" ::: "memory")

// ===========================================================================
// Transpose: dst[b][col][row] = src[b][row][col].  rows=C_, cols=L_.
// ===========================================================================
__global__ __launch_bounds__(256) void transpose_kernel(const float* __restrict__ src,
                                                        float* __restrict__ dst,
                                                        int rows, int cols) {
    __shared__ float tile[32][33];
    const int b = blockIdx.z;
    const int r0 = blockIdx.y * 32;
    const int c0 = blockIdx.x * 32;
    const int tx = threadIdx.x & 31, ty = threadIdx.x >> 5;
    const float* sb = src + (size_t)b * rows * cols;
    float* db = dst + (size_t)b * rows * cols;
#pragma unroll
    for (int i = 0; i < 4; i++)
        tile[ty + i * 8][tx] = sb[(size_t)(r0 + ty + i * 8) * cols + c0 + tx];
    __syncthreads();
#pragma unroll
    for (int i = 0; i < 4; i++)
        db[(size_t)(c0 + ty + i * 8) * rows + r0 + tx] = tile[tx][ty + i * 8];
}

// ===========================================================================
// Fused QKV projection, TRANSPOSED tf32 output. Register-prefetch pipelined.
//   Y[b][l][o] = sum_c XT[b][l][c] * W[o][c] + bias[o]
// ===========================================================================
__global__ __launch_bounds__(256) void qkv_mma(const float* __restrict__ wq,
                                               const float* __restrict__ bq,
                                               const float* __restrict__ wk,
                                               const float* __restrict__ bk,
                                               const float* __restrict__ wv,
                                               const float* __restrict__ bv,
                                               const float* __restrict__ XT,
                                               float* __restrict__ q,
                                               float* __restrict__ k,
                                               float* __restrict__ v) {
    __shared__ float As[128][36];   // XT tile [l][c]
    __shared__ float Bs[128][36];   // W  tile [o][c]
    const int tid = threadIdx.x;
    const int wid = tid >> 5, lane = tid & 31;
    const int g = lane >> 2, tig = lane & 3;
    const int warpM = wid & 3, warpN = wid >> 2;
    const int pid = blockIdx.z % 3;
    const int b   = blockIdx.z / 3;
    const int l0  = blockIdx.y * 128;
    const int o0  = blockIdx.x * 128;

    const float* W    = (pid == 0) ? wq : (pid == 1) ? wk : wv;
    const float* bias = (pid == 0) ? bq : (pid == 1) ? bk : bv;
    float* Y          = (pid == 0) ? q  : (pid == 1) ? k  : v;

    const int rowb = tid >> 3;
    const int c4   = (tid & 7) * 4;

    float acc[2][8][4];
#pragma unroll
    for (int mt = 0; mt < 2; mt++)
#pragma unroll
        for (int nt = 0; nt < 8; nt++)
#pragma unroll
            for (int i = 0; i < 4; i++) acc[mt][nt][i] = 0.f;

    float4 xr[4], wr[4];
#pragma unroll
    for (int it = 0; it < 4; it++) {
        int row = it * 32 + rowb;
        xr[it] = *(const float4*)(XT + ((size_t)b * L_ + l0 + row) * C_ + c4);
        wr[it] = *(const float4*)(W + (size_t)(o0 + row) * C_ + c4);
    }

    for (int ct = 0; ct < C_ / 32; ct++) {
#pragma unroll
        for (int it = 0; it < 4; it++) {
            int row = it * 32 + rowb;
            *(uint4*)&As[row][c4] = make_uint4(f2tf32(xr[it].x), f2tf32(xr[it].y),
                                               f2tf32(xr[it].z), f2tf32(xr[it].w));
            *(uint4*)&Bs[row][c4] = make_uint4(f2tf32(wr[it].x), f2tf32(wr[it].y),
                                               f2tf32(wr[it].z), f2tf32(wr[it].w));
        }
        __syncthreads();
        if (ct + 1 < C_ / 32) {
            const int c0n = (ct + 1) * 32;
#pragma unroll
            for (int it = 0; it < 4; it++) {
                int row = it * 32 + rowb;
                xr[it] = *(const float4*)(XT + ((size_t)b * L_ + l0 + row) * C_ + c0n + c4);
                wr[it] = *(const float4*)(W + (size_t)(o0 + row) * C_ + c0n + c4);
            }
        }
#pragma unroll
        for (int ks = 0; ks < 4; ks++) {
            const int k0 = ks * 8;
            uint32_t a[2][4];
#pragma unroll
            for (int mt = 0; mt < 2; mt++) {
                int rb = warpM * 32 + mt * 16;
                a[mt][0] = __float_as_uint(As[rb + g][k0 + tig]);
                a[mt][1] = __float_as_uint(As[rb + g + 8][k0 + tig]);
                a[mt][2] = __float_as_uint(As[rb + g][k0 + tig + 4]);
                a[mt][3] = __float_as_uint(As[rb + g + 8][k0 + tig + 4]);
            }
#pragma unroll
            for (int nt = 0; nt < 8; nt++) {
                int nb = warpN * 64 + nt * 8;
                uint32_t b0 = __float_as_uint(Bs[nb + g][k0 + tig]);
                uint32_t b1 = __float_as_uint(Bs[nb + g][k0 + tig + 4]);
#pragma unroll
                for (int mt = 0; mt < 2; mt++)
                    mma_tf32(acc[mt][nt], a[mt], b0, b1);
            }
        }
        __syncthreads();
    }

#pragma unroll
    for (int mt = 0; mt < 2; mt++) {
        int lr0 = l0 + warpM * 32 + mt * 16;
        float* y0 = Y + ((size_t)b * L_ + lr0 + g) * C_;
        float* y1 = Y + ((size_t)b * L_ + lr0 + g + 8) * C_;
#pragma unroll
        for (int nt = 0; nt < 8; nt++) {
            int col = o0 + warpN * 64 + nt * 8 + 2 * tig;
            float bv0 = bias[col], bv1 = bias[col + 1];
            *(float2*)(y0 + col) = make_float2(__uint_as_float(f2tf32(acc[mt][nt][0] + bv0)),
                                               __uint_as_float(f2tf32(acc[mt][nt][1] + bv1)));
            *(float2*)(y1 + col) = make_float2(__uint_as_float(f2tf32(acc[mt][nt][2] + bv0)),
                                               __uint_as_float(f2tf32(acc[mt][nt][3] + bv1)));
        }
    }
}

// ===========================================================================
// O projection, register-prefetch pipelined:
//   out[b][o][l] = sum_c W[o][c] * resT[b][l][c] + bias[o]
// ===========================================================================
__global__ __launch_bounds__(256) void proj_mma(const float* __restrict__ W,
                                                const float* __restrict__ bias,
                                                const float* __restrict__ XT,
                                                float* __restrict__ Y) {
    __shared__ float As[128][36];   // W  [o][c]
    __shared__ float Bs[128][36];   // XT [l][c]
    const int tid = threadIdx.x;
    const int wid = tid >> 5, lane = tid & 31;
    const int g = lane >> 2, tig = lane & 3;
    const int warpM = wid & 3, warpN = wid >> 2;
    const int b  = blockIdx.z;
    const int o0 = blockIdx.y * 128;
    const int l0 = blockIdx.x * 128;

    const int rowb = tid >> 3;
    const int c4   = (tid & 7) * 4;

    float acc[2][8][4];
#pragma unroll
    for (int mt = 0; mt < 2; mt++)
#pragma unroll
        for (int nt = 0; nt < 8; nt++)
#pragma unroll
            for (int i = 0; i < 4; i++) acc[mt][nt][i] = 0.f;

    float4 wr[4], xr[4];
#pragma unroll
    for (int it = 0; it < 4; it++) {
        int row = it * 32 + rowb;
        wr[it] = *(const float4*)(W + (size_t)(o0 + row) * C_ + c4);
        xr[it] = *(const float4*)(XT + ((size_t)b * L_ + l0 + row) * C_ + c4);
    }

    for (int ct = 0; ct < C_ / 32; ct++) {
#pragma unroll
        for (int it = 0; it < 4; it++) {
            int row = it * 32 + rowb;
            *(uint4*)&As[row][c4] = make_uint4(f2tf32(wr[it].x), f2tf32(wr[it].y),
                                               f2tf32(wr[it].z), f2tf32(wr[it].w));
            *(uint4*)&Bs[row][c4] = make_uint4(f2tf32(xr[it].x), f2tf32(xr[it].y),
                                               f2tf32(xr[it].z), f2tf32(xr[it].w));
        }
        __syncthreads();
        if (ct + 1 < C_ / 32) {
            const int c0n = (ct + 1) * 32;
#pragma unroll
            for (int it = 0; it < 4; it++) {
                int row = it * 32 + rowb;
                wr[it] = *(const float4*)(W + (size_t)(o0 + row) * C_ + c0n + c4);
                xr[it] = *(const float4*)(XT + ((size_t)b * L_ + l0 + row) * C_ + c0n + c4);
            }
        }
#pragma unroll
        for (int ks = 0; ks < 4; ks++) {
            const int k0 = ks * 8;
            uint32_t a[2][4];
#pragma unroll
            for (int mt = 0; mt < 2; mt++) {
                int rb = warpM * 32 + mt * 16;
                a[mt][0] = __float_as_uint(As[rb + g][k0 + tig]);
                a[mt][1] = __float_as_uint(As[rb + g + 8][k0 + tig]);
                a[mt][2] = __float_as_uint(As[rb + g][k0 + tig + 4]);
                a[mt][3] = __float_as_uint(As[rb + g + 8][k0 + tig + 4]);
            }
#pragma unroll
            for (int nt = 0; nt < 8; nt++) {
                int nb = warpN * 64 + nt * 8;
                uint32_t b0 = __float_as_uint(Bs[nb + g][k0 + tig]);
                uint32_t b1 = __float_as_uint(Bs[nb + g][k0 + tig + 4]);
#pragma unroll
                for (int mt = 0; mt < 2; mt++)
                    mma_tf32(acc[mt][nt], a[mt], b0, b1);
            }
        }
        __syncthreads();
    }

#pragma unroll
    for (int mt = 0; mt < 2; mt++) {
        int r0 = o0 + warpM * 32 + mt * 16;
        float bv0 = bias[r0 + g];
        float bv1 = bias[r0 + g + 8];
        float* y0 = Y + ((size_t)b * C_ + r0 + g) * L_;
        float* y1 = Y + ((size_t)b * C_ + r0 + g + 8) * L_;
#pragma unroll
        for (int nt = 0; nt < 8; nt++) {
            int col = l0 + warpN * 64 + nt * 8 + 2 * tig;
            *(float2*)(y0 + col) = make_float2(acc[mt][nt][0] + bv0, acc[mt][nt][1] + bv0);
            *(float2*)(y1 + col) = make_float2(acc[mt][nt][2] + bv1, acc[mt][nt][3] + bv1);
        }
    }
}

// ===========================================================================
// Tensor-core flash attention, cp.async double-buffered K/V, 2 CTAs/SM.
// Block: 64 q-rows of one (b,h); 4 warps; warp = 16 rows x 64 cols.
// Q fragments live in registers; the Q staging buffer is reused as P
// (rows are warp-private). Eks borrows K-buffer-1 during the prologue.
// Arithmetic identical to R9 (same op order / rounding).
// ===========================================================================
#define AP 68
#define KVT 4352                 // floats per 64x68 tile buffer
// smem float offsets
#define SM_PQ  0                 // Q-stage then P: [64][68]
#define SM_K   4352              // 2 x [64][68]
#define SM_V   13056             // 2 x [64][68]
#define SM_EV  21760             // [9][64]
#define SM_QEK 22336             // [64][9]
#define ATTN_SMEMF 22912         // total floats (91648 bytes)

__global__ __launch_bounds__(128) void attn_mma(const float* __restrict__ erk,
                                                const float* __restrict__ erv) {
    extern __shared__ float sm[];
    float* PQ  = sm + SM_PQ;
    float* Ks  = sm + SM_K;
    float* Vs  = sm + SM_V;
    float* Evs = sm + SM_EV;
    float* qEk = sm + SM_QEK;
    float* Eks = Ks + KVT;       // prologue-only, overlaps K buffer 1

    const int tid = threadIdx.x;
    const int w = tid >> 5, lane = tid & 31;
    const int g = lane >> 2, tig = lane & 3;
    const int rb = w * 16;
    const int i0 = blockIdx.x * 64;
    const int bh = blockIdx.y;
    const int b = bh / H_, h = bh % H_;

    const float* QT = g_qT + (size_t)b * L_ * C_ + h * D_;
    const float* KT = g_kT + (size_t)b * L_ * C_ + h * D_;
    const float* VT = g_vT + (size_t)b * L_ * C_ + h * D_;

    const uint32_t ks_u = smem_u32(Ks);
    const uint32_t vs_u = smem_u32(Vs);
    const int cp_r  = tid >> 3;          // 0..15 (row base per it: it*16+cp_r)
    const int cp_d4 = (tid & 7) * 8;     // two float4s per row half? no:
    // 64 floats/row, 8 threads/row x 8 floats? Use: 16 rows per pass, 8 thr/row
    // thread covers 8 floats => two cp.async16. Simpler mapping below.

    // Prefetch K/V tile 0 into buffer 0: 64 rows x 64 floats; 128 thr.
    // Each pass: 32 rows (4 thr/row x 16B). it=0,1 cover 64 rows.
    {
        const int r_ = tid >> 2;          // 0..31
        const int d4_ = (tid & 3) * 16;   // byte offset 0,64,... -> floats *4
#pragma unroll
        for (int it = 0; it < 2; it++) {
            int r = it * 32 + r_;
            uint32_t so = (uint32_t)(r * AP) * 4 + d4_ * 4;
            const float* kg = KT + (size_t)r * C_ + d4_;
            const float* vg = VT + (size_t)r * C_ + d4_;
            cp_async16(ks_u + so, kg);
            cp_async16(ks_u + so + 16, kg + 4);
            cp_async16(ks_u + so + 32, kg + 8);
            cp_async16(ks_u + so + 48, kg + 12);
            cp_async16(vs_u + so, vg);
            cp_async16(vs_u + so + 16, vg + 4);
            cp_async16(vs_u + so + 32, vg + 8);
            cp_async16(vs_u + so + 48, vg + 12);
        }
    }
    CP_COMMIT();

    // Stage Q (pre-scaled by 1/8, exact) into PQ + embedding tables.
#pragma unroll
    for (int it = 0; it < 8; it++) {
        int idx = it * 128 + tid;
        int r = idx >> 4, d4 = (idx & 15) * 4;
        float4 q4 = *(const float4*)(QT + (size_t)(i0 + r) * C_ + d4);
        PQ[r * AP + d4 + 0] = q4.x * 0.125f;
        PQ[r * AP + d4 + 1] = q4.y * 0.125f;
        PQ[r * AP + d4 + 2] = q4.z * 0.125f;
        PQ[r * AP + d4 + 3] = q4.w * 0.125f;
    }
    for (int e = tid; e < NW_ * 64; e += 128) {
        int dd = e >> 6, r = e & 63;
        Eks[dd * 64 + r] = erk[(h * NW_ + dd) * 64 + r];
        Evs[dd * 64 + r] = erv[(h * NW_ + dd) * 64 + r];
    }
    __syncthreads();

    // qEk[i][dd] = (q_i/8) . Ek[dd]
    for (int e = tid; e < 64 * NW_; e += 128) {
        int dd = e >> 6, i = e & 63;
        float s = 0.f;
#pragma unroll
        for (int d = 0; d < 64; d++) s += PQ[i * AP + d] * Eks[dd * 64 + d];
        qEk[i * NW_ + dd] = s;
    }

    // Q fragments into registers (own rows only — no cross-warp hazard).
    uint32_t qf[8][4];
#pragma unroll
    for (int ks = 0; ks < 8; ks++) {
        const int k0 = ks * 8;
        qf[ks][0] = __float_as_uint(PQ[(rb + g) * AP + k0 + tig]);
        qf[ks][1] = __float_as_uint(PQ[(rb + g + 8) * AP + k0 + tig]);
        qf[ks][2] = __float_as_uint(PQ[(rb + g) * AP + k0 + tig + 4]);
        qf[ks][3] = __float_as_uint(PQ[(rb + g + 8) * AP + k0 + tig + 4]);
    }
    __syncthreads();  // qEk visible; Eks reads done before buf1 prefetch;
                      // all Q reads done before P overwrites PQ.

    float m0 = -1e30f, m1 = -1e30f, l0 = 0.f, l1 = 0.f;
    float o[8][4];
#pragma unroll
    for (int nt = 0; nt < 8; nt++)
#pragma unroll
        for (int i = 0; i < 4; i++) o[nt][i] = 0.f;

    const int qi0 = i0 + rb + g;
    const int qi1 = qi0 + 8;
    const int NT = L_ / 64;

    for (int jt = 0; jt < NT; jt++) {
        const int j0 = jt * 64;
        const int cur = jt & 1;
        if (jt + 1 < NT) {
            const float* Kn = KT + (size_t)(j0 + 64) * C_;
            const float* Vn = VT + (size_t)(j0 + 64) * C_;
            uint32_t bo = (uint32_t)((cur ^ 1) * KVT) * 4;
            const int r_ = tid >> 2;
            const int d4_ = (tid & 3) * 16;
#pragma unroll
            for (int it = 0; it < 2; it++) {
                int r = it * 32 + r_;
                uint32_t so = bo + (uint32_t)(r * AP) * 4 + d4_ * 4;
                const float* kg = Kn + (size_t)r * C_ + d4_;
                const float* vg = Vn + (size_t)r * C_ + d4_;
                cp_async16(ks_u + so, kg);
                cp_async16(ks_u + so + 16, kg + 4);
                cp_async16(ks_u + so + 32, kg + 8);
                cp_async16(ks_u + so + 48, kg + 12);
                cp_async16(vs_u + so, vg);
                cp_async16(vs_u + so + 16, vg + 4);
                cp_async16(vs_u + so + 32, vg + 8);
                cp_async16(vs_u + so + 48, vg + 12);
            }
            CP_COMMIT();
            CP_WAIT1();
        } else {
            CP_WAIT0();
        }
        __syncthreads();   // current K/V visible; prev tile's smem reads done

        const float* Kc = Ks + cur * KVT;
        const float* Vc = Vs + cur * KVT;

        // S = (Q/8) K^T
        float s[8][4];
#pragma unroll
        for (int nt = 0; nt < 8; nt++)
#pragma unroll
            for (int i = 0; i < 4; i++) s[nt][i] = 0.f;
#pragma unroll
        for (int ks = 0; ks < 8; ks++) {
            const int k0 = ks * 8;
#pragma unroll
            for (int nt = 0; nt < 8; nt++) {
                uint32_t b0 = __float_as_uint(Kc[(nt * 8 + g) * AP + k0 + tig]);
                uint32_t b1 = __float_as_uint(Kc[(nt * 8 + g) * AP + k0 + tig + 4]);
                mma_tf32(s[nt], qf[ks], b0, b1);
            }
        }

        // Relative-K band bias (scale folded into qEk)
        const bool near = (j0 + 63 >= i0 - 4) && (j0 <= i0 + 67);
        if (near) {
#pragma unroll
            for (int nt = 0; nt < 8; nt++) {
#pragma unroll
                for (int c = 0; c < 2; c++) {
                    int j = j0 + nt * 8 + 2 * tig + c;
                    int d0 = j - qi0;
                    if (d0 >= -4 && d0 <= 4) s[nt][c] += qEk[(rb + g) * NW_ + d0 + 4];
                    int d1 = j - qi1;
                    if (d1 >= -4 && d1 <= 4) s[nt][c + 2] += qEk[(rb + g + 8) * NW_ + d1 + 4];
                }
            }
        }

        // Online softmax (4-lane row reductions)
        float tm0 = -1e30f, tm1 = -1e30f;
#pragma unroll
        for (int nt = 0; nt < 8; nt++) {
            tm0 = fmaxf(tm0, fmaxf(s[nt][0], s[nt][1]));
            tm1 = fmaxf(tm1, fmaxf(s[nt][2], s[nt][3]));
        }
#pragma unroll
        for (int off = 1; off <= 2; off <<= 1) {
            tm0 = fmaxf(tm0, __shfl_xor_sync(0xffffffffu, tm0, off));
            tm1 = fmaxf(tm1, __shfl_xor_sync(0xffffffffu, tm1, off));
        }
        float mn0 = fmaxf(m0, tm0), mn1 = fmaxf(m1, tm1);
        float ts0 = 0.f, ts1 = 0.f;
#pragma unroll
        for (int nt = 0; nt < 8; nt++) {
            s[nt][0] = __expf(s[nt][0] - mn0);
            s[nt][1] = __expf(s[nt][1] - mn0);
            s[nt][2] = __expf(s[nt][2] - mn1);
            s[nt][3] = __expf(s[nt][3] - mn1);
            ts0 += s[nt][0] + s[nt][1];
            ts1 += s[nt][2] + s[nt][3];
        }
#pragma unroll
        for (int off = 1; off <= 2; off <<= 1) {
            ts0 += __shfl_xor_sync(0xffffffffu, ts0, off);
            ts1 += __shfl_xor_sync(0xffffffffu, ts1, off);
        }
        float al0 = __expf(m0 - mn0), al1 = __expf(m1 - mn1);
        l0 = l0 * al0 + ts0;  m0 = mn0;
        l1 = l1 * al1 + ts1;  m1 = mn1;
#pragma unroll
        for (int nt = 0; nt < 8; nt++) {
            o[nt][0] *= al0; o[nt][1] *= al0;
            o[nt][2] *= al1; o[nt][3] *= al1;
        }

        // Stage P (tf32-rounded) into warp-private rows of PQ.
#pragma unroll
        for (int nt = 0; nt < 8; nt++) {
            int col = nt * 8 + 2 * tig;
            *(float2*)&PQ[(rb + g) * AP + col] =
                make_float2(__uint_as_float(f2tf32(s[nt][0])),
                            __uint_as_float(f2tf32(s[nt][1])));
            *(float2*)&PQ[(rb + g + 8) * AP + col] =
                make_float2(__uint_as_float(f2tf32(s[nt][2])),
                            __uint_as_float(f2tf32(s[nt][3])));
        }
        __syncwarp();

        // O += P V
#pragma unroll
        for (int ks = 0; ks < 8; ks++) {
            const int k0 = ks * 8;
            uint32_t a[4];
            a[0] = __float_as_uint(PQ[(rb + g) * AP + k0 + tig]);
            a[1] = __float_as_uint(PQ[(rb + g + 8) * AP + k0 + tig]);
            a[2] = __float_as_uint(PQ[(rb + g) * AP + k0 + tig + 4]);
            a[3] = __float_as_uint(PQ[(rb + g + 8) * AP + k0 + tig + 4]);
#pragma unroll
            for (int nt = 0; nt < 8; nt++) {
                uint32_t b0 = __float_as_uint(Vc[(k0 + tig) * AP + nt * 8 + g]);
                uint32_t b1 = __float_as_uint(Vc[(k0 + tig + 4) * AP + nt * 8 + g]);
                mma_tf32(o[nt], a, b0, b1);
            }
        }

        // Relative-V band
        if (near) {
#pragma unroll
            for (int dd = 0; dd < NW_; dd++) {
                int j0r = qi0 + dd - 4 - j0;
                if (j0r >= 0 && j0r < 64) {
                    float p = PQ[(rb + g) * AP + j0r];
#pragma unroll
                    for (int nt = 0; nt < 8; nt++) {
                        int col = nt * 8 + 2 * tig;
                        o[nt][0] += p * Evs[dd * 64 + col];
                        o[nt][1] += p * Evs[dd * 64 + col + 1];
                    }
                }
                int j1r = qi1 + dd - 4 - j0;
                if (j1r >= 0 && j1r < 64) {
                    float p = PQ[(rb + g + 8) * AP + j1r];
#pragma unroll
                    for (int nt = 0; nt < 8; nt++) {
                        int col = nt * 8 + 2 * tig;
                        o[nt][2] += p * Evs[dd * 64 + col];
                        o[nt][3] += p * Evs[dd * 64 + col + 1];
                    }
                }
            }
        }
        __syncthreads();   // all reads of buf cur done before re-prefetch
    }

    // Epilogue: normalize, store resT[b][l][h*64+dim].
    float inv0 = 1.0f / l0, inv1 = 1.0f / l1;
    float* r0p = g_resT + ((size_t)b * L_ + qi0) * C_ + h * D_;
    float* r1p = g_resT + ((size_t)b * L_ + qi1) * C_ + h * D_;
#pragma unroll
    for (int nt = 0; nt < 8; nt++) {
        int col = nt * 8 + 2 * tig;
        *(float2*)(r0p + col) = make_float2(o[nt][0] * inv0, o[nt][1] * inv0);
        *(float2*)(r1p + col) = make_float2(o[nt][2] * inv1, o[nt][3] * inv1);
    }
}

// ---------------------------------------------------------------------------
extern "C" void kernel_launch(void* const* d_in, const int* in_sizes, int n_in,
                              void* d_out, int out_size) {
    const float* x   = (const float*)d_in[0];
    const float* wq  = (const float*)d_in[1];
    const float* bq  = (const float*)d_in[2];
    const float* wk  = (const float*)d_in[3];
    const float* bk  = (const float*)d_in[4];
    const float* wv  = (const float*)d_in[5];
    const float* bv  = (const float*)d_in[6];
    const float* wo  = (const float*)d_in[7];
    const float* bo  = (const float*)d_in[8];
    const float* erk = (const float*)d_in[9];
    const float* erv = (const float*)d_in[10];
    float* out = (float*)d_out;

    float *gqT, *gkT, *gvT, *gxT, *gresT;
    cudaGetSymbolAddress((void**)&gqT,   g_qT);
    cudaGetSymbolAddress((void**)&gkT,   g_kT);
    cudaGetSymbolAddress((void**)&gvT,   g_vT);
    cudaGetSymbolAddress((void**)&gxT,   g_xT);
    cudaGetSymbolAddress((void**)&gresT, g_resT);

    const int attn_smem = ATTN_SMEMF * 4;  // 91648 bytes -> 2 CTAs/SM
    cudaFuncSetAttribute(attn_mma, cudaFuncAttributeMaxDynamicSharedMemorySize,
                         attn_smem);

    // x[b][c][l] -> xT[b][l][c]
    dim3 tgrid(L_ / 32, C_ / 32, B_);
    transpose_kernel<<<tgrid, 256>>>(x, gxT, C_, L_);

    // Fused QKV, transposed tf32 outputs
    dim3 qgrid(C_ / 128, L_ / 128, B_ * 3);   // (3, 8, 24)
    qkv_mma<<<qgrid, 256>>>(wq, bq, wk, bk, wv, bv, gxT, gqT, gkT, gvT);

    // Tensor-core attention (64 q-rows per block, 2 CTAs/SM)
    dim3 agrid(L_ / 64, B_ * H_);             // (16, 48)
    attn_mma<<<agrid, 128, attn_smem>>>(erk, erv);

    // O projection
    dim3 ogrid(L_ / 128, C_ / 128, B_);       // (8, 3, 8)
    proj_mma<<<ogrid, 256>>>(wo, bo, gresT, out);
}

// round 11
// speedup vs baseline: 1.1857x; 1.1857x over previous
#include <cuda_runtime.h>
#include <cstdint>

#define B_ 8
#define C_ 384
#define L_ 1024
#define H_ 6
#define D_ 64
#define NW_ 9   // 2*window+1

// Scratch (allocation-free rule: device globals). All [b][l][c] layout.
__device__ float g_qT[B_*L_*C_];
__device__ float g_kT[B_*L_*C_];
__device__ float g_vT[B_*L_*C_];
__device__ float g_xT[B_*L_*C_];    // tf32-rounded
__device__ float g_resT[B_*L_*C_];  // tf32-rounded (attn epilogue)
__device__ float g_wr[4*C_*C_];     // tf32-rounded wq,wk,wv,wo

__device__ __forceinline__ uint32_t f2tf32(float f) {
    uint32_t r;
    asm("cvt.rna.tf32.f32 %0, %1;" : "=r"(r) : "f"(f));
    return r;
}

__device__ __forceinline__ void mma_tf32(float* d, const uint32_t* a,
                                         uint32_t b0, uint32_t b1) {
    asm volatile("mma.sync.aligned.m16n8k8.row.col.f32.tf32.tf32.f32 "
                 "{%0,%1,%2,%3}, {%4,%5,%6,%7}, {%8,%9}, {%0,%1,%2,%3};"
                 : "+f"(d[0]), "+f"(d[1]), "+f"(d[2]), "+f"(d[3])
                 : "r"(a[0]), "r"(a[1]), "r"(a[2]), "r"(a[3]),
                   "r"(b0), "r"(b1));
}

__device__ __forceinline__ uint32_t smem_u32(const void* p) {
    uint32_t a;
    asm("{ .reg .u64 t; cvta.to.shared.u64 t, %1; cvt.u32.u64 %0, t; }"
        : "=r"(a) : "l"(p));
    return a;
}
__device__ __forceinline__ void cp_async16(uint32_t s, const void* g) {
    asm volatile("cp.async.cg.shared.global [%0], [%1], 16;" :: "r"(s), "l"(g));
}
#define CP_COMMIT() asm volatile("cp.async.commit_group;" ::: "memory")
#define CP_WAIT1()  asm volatile("cp.async.wait_group 1;" ::: "memory")
#define CP_WAIT0()  asm volatile("cp.async.wait_group 0;" ::: "memory")

// ===========================================================================
// Transpose + tf32 round: dst[b][col][row] = rna_tf32(src[b][row][col]).
// ===========================================================================
__global__ __launch_bounds__(256) void transpose_kernel(const float* __restrict__ src,
                                                        float* __restrict__ dst,
                                                        int rows, int cols) {
    __shared__ float tile[32][33];
    const int b = blockIdx.z;
    const int r0 = blockIdx.y * 32;
    const int c0 = blockIdx.x * 32;
    const int tx = threadIdx.x & 31, ty = threadIdx.x >> 5;
    const float* sb = src + (size_t)b * rows * cols;
    float* db = dst + (size_t)b * rows * cols;
#pragma unroll
    for (int i = 0; i < 4; i++)
        tile[ty + i * 8][tx] = sb[(size_t)(r0 + ty + i * 8) * cols + c0 + tx];
    __syncthreads();
#pragma unroll
    for (int i = 0; i < 4; i++)
        db[(size_t)(c0 + ty + i * 8) * rows + r0 + tx] =
            __uint_as_float(f2tf32(tile[tx][ty + i * 8]));
}

// ===========================================================================
// Round the four weight matrices to tf32 once.
// grid: (C_*C_/1024, 4); 256 thr, float4 per thread.
// ===========================================================================
__global__ __launch_bounds__(256) void round_w(const float* __restrict__ w0,
                                               const float* __restrict__ w1,
                                               const float* __restrict__ w2,
                                               const float* __restrict__ w3,
                                               float* __restrict__ dst) {
    const int m = blockIdx.y;
    const float* src = (m == 0) ? w0 : (m == 1) ? w1 : (m == 2) ? w2 : w3;
    int idx = (blockIdx.x * 256 + threadIdx.x) * 4;
    float4 v = *(const float4*)(src + idx);
    uint4 t = make_uint4(f2tf32(v.x), f2tf32(v.y), f2tf32(v.z), f2tf32(v.w));
    *(uint4*)(dst + (size_t)m * C_ * C_ + idx) = t;
}

// ===========================================================================
// cp.async double-buffered tf32 GEMM core (inputs pre-rounded).
// Tile 128x128, K chunks of 32. Smem: 4 buffers of [128][36].
// A rows from Ag (stride C_), B rows from Bg (stride C_); D = A * B^T.
// ===========================================================================
#define GEMM_SMEMF (4 * 128 * 36)   // 18432 floats = 73728 bytes

__device__ __forceinline__ void gemm_stage(uint32_t sa, uint32_t sb,
                                           const float* Ag, const float* Bg,
                                           int c0, int tid) {
    const int r_ = tid >> 3;          // 0..31
    const int u  = (tid & 7) * 4;     // float offset (16B units)
#pragma unroll
    for (int it = 0; it < 4; it++) {
        int row = it * 32 + r_;
        uint32_t so = (uint32_t)(row * 36 + u) * 4;
        cp_async16(sa + so, Ag + (size_t)row * C_ + c0 + u);
        cp_async16(sb + so, Bg + (size_t)row * C_ + c0 + u);
    }
}

__device__ __forceinline__ void gemm_core(float acc[2][8][4], float* smem,
                                          const float* Ag, const float* Bg,
                                          int tid) {
    const int lane = tid & 31;
    const int g = lane >> 2, tig = lane & 3;
    const int wid = tid >> 5;
    const int warpM = wid & 3, warpN = wid >> 2;
    float* As = smem;                 // 2 x [128][36]
    float* Bs = smem + 2 * 128 * 36;
    const uint32_t as_u = smem_u32(As);
    const uint32_t bs_u = smem_u32(Bs);
    const uint32_t bufb = 128 * 36 * 4;   // bytes per buffer

    gemm_stage(as_u, bs_u, Ag, Bg, 0, tid);
    CP_COMMIT();

    for (int ct = 0; ct < C_ / 32; ct++) {
        const int cur = ct & 1;
        if (ct + 1 < C_ / 32) {
            gemm_stage(as_u + (cur ^ 1) * bufb, bs_u + (cur ^ 1) * bufb,
                       Ag, Bg, (ct + 1) * 32, tid);
            CP_COMMIT();
            CP_WAIT1();
        } else {
            CP_WAIT0();
        }
        __syncthreads();
        const float* Ac = As + cur * 128 * 36;
        const float* Bc = Bs + cur * 128 * 36;
#pragma unroll
        for (int ks = 0; ks < 4; ks++) {
            const int k0 = ks * 8;
            uint32_t a[2][4];
#pragma unroll
            for (int mt = 0; mt < 2; mt++) {
                int rb = warpM * 32 + mt * 16;
                a[mt][0] = __float_as_uint(Ac[(rb + g) * 36 + k0 + tig]);
                a[mt][1] = __float_as_uint(Ac[(rb + g + 8) * 36 + k0 + tig]);
                a[mt][2] = __float_as_uint(Ac[(rb + g) * 36 + k0 + tig + 4]);
                a[mt][3] = __float_as_uint(Ac[(rb + g + 8) * 36 + k0 + tig + 4]);
            }
#pragma unroll
            for (int nt = 0; nt < 8; nt++) {
                int nb = warpN * 64 + nt * 8;
                uint32_t b0 = __float_as_uint(Bc[(nb + g) * 36 + k0 + tig]);
                uint32_t b1 = __float_as_uint(Bc[(nb + g) * 36 + k0 + tig + 4]);
#pragma unroll
                for (int mt = 0; mt < 2; mt++)
                    mma_tf32(acc[mt][nt], a[mt], b0, b1);
            }
        }
        __syncthreads();
    }
}

// ===========================================================================
// Fused QKV projection, TRANSPOSED tf32 output:
//   Y[b][l][o] = sum_c XT[b][l][c] * W[o][c] + bias[o]
// A = XT rows (M=l), B = W rows (N=o).
// ===========================================================================
__global__ __launch_bounds__(256) void qkv_mma(const float* __restrict__ Wr,
                                               const float* __restrict__ bq,
                                               const float* __restrict__ bk,
                                               const float* __restrict__ bv,
                                               const float* __restrict__ XT,
                                               float* __restrict__ q,
                                               float* __restrict__ k,
                                               float* __restrict__ v) {
    extern __shared__ float smem[];
    const int tid = threadIdx.x;
    const int lane = tid & 31;
    const int g = lane >> 2, tig = lane & 3;
    const int wid = tid >> 5;
    const int warpM = wid & 3, warpN = wid >> 2;
    const int pid = blockIdx.z % 3;
    const int b   = blockIdx.z / 3;
    const int l0  = blockIdx.y * 128;
    const int o0  = blockIdx.x * 128;

    const float* bias = (pid == 0) ? bq : (pid == 1) ? bk : bv;
    float* Y          = (pid == 0) ? q  : (pid == 1) ? k  : v;
    const float* Ag = XT + ((size_t)b * L_ + l0) * C_;
    const float* Bg = g_wr + (size_t)pid * C_ * C_ + (size_t)o0 * C_;

    float acc[2][8][4];
#pragma unroll
    for (int mt = 0; mt < 2; mt++)
#pragma unroll
        for (int nt = 0; nt < 8; nt++)
#pragma unroll
            for (int i = 0; i < 4; i++) acc[mt][nt][i] = 0.f;

    gemm_core(acc, smem, Ag, Bg, tid);

#pragma unroll
    for (int mt = 0; mt < 2; mt++) {
        int lr0 = l0 + warpM * 32 + mt * 16;
        float* y0 = Y + ((size_t)b * L_ + lr0 + g) * C_;
        float* y1 = Y + ((size_t)b * L_ + lr0 + g + 8) * C_;
#pragma unroll
        for (int nt = 0; nt < 8; nt++) {
            int col = o0 + warpN * 64 + nt * 8 + 2 * tig;
            float bv0 = bias[col], bv1 = bias[col + 1];
            *(float2*)(y0 + col) = make_float2(__uint_as_float(f2tf32(acc[mt][nt][0] + bv0)),
                                               __uint_as_float(f2tf32(acc[mt][nt][1] + bv1)));
            *(float2*)(y1 + col) = make_float2(__uint_as_float(f2tf32(acc[mt][nt][2] + bv0)),
                                               __uint_as_float(f2tf32(acc[mt][nt][3] + bv1)));
        }
    }
}

// ===========================================================================
// O projection: out[b][o][l] = sum_c W[o][c] * resT[b][l][c] + bias[o]
// A = W rows (M=o), B = resT rows (N=l).
// ===========================================================================
__global__ __launch_bounds__(256) void proj_mma(const float* __restrict__ bias,
                                                const float* __restrict__ XT,
                                                float* __restrict__ Y) {
    extern __shared__ float smem[];
    const int tid = threadIdx.x;
    const int lane = tid & 31;
    const int g = lane >> 2, tig = lane & 3;
    const int wid = tid >> 5;
    const int warpM = wid & 3, warpN = wid >> 2;
    const int b  = blockIdx.z;
    const int o0 = blockIdx.y * 128;
    const int l0 = blockIdx.x * 128;

    const float* Ag = g_wr + (size_t)3 * C_ * C_ + (size_t)o0 * C_;
    const float* Bg = XT + ((size_t)b * L_ + l0) * C_;

    float acc[2][8][4];
#pragma unroll
    for (int mt = 0; mt < 2; mt++)
#pragma unroll
        for (int nt = 0; nt < 8; nt++)
#pragma unroll
            for (int i = 0; i < 4; i++) acc[mt][nt][i] = 0.f;

    gemm_core(acc, smem, Ag, Bg, tid);

#pragma unroll
    for (int mt = 0; mt < 2; mt++) {
        int r0 = o0 + warpM * 32 + mt * 16;
        float bv0 = bias[r0 + g];
        float bv1 = bias[r0 + g + 8];
        float* y0 = Y + ((size_t)b * C_ + r0 + g) * L_;
        float* y1 = Y + ((size_t)b * C_ + r0 + g + 8) * L_;
#pragma unroll
        for (int nt = 0; nt < 8; nt++) {
            int col = l0 + warpN * 64 + nt * 8 + 2 * tig;
            *(float2*)(y0 + col) = make_float2(acc[mt][nt][0] + bv0, acc[mt][nt][1] + bv0);
            *(float2*)(y1 + col) = make_float2(acc[mt][nt][2] + bv1, acc[mt][nt][3] + bv1);
        }
    }
}

// ===========================================================================
// Tensor-core flash attention (R9 shape), cp.async double-buffered K/V.
// Block: 128 q-rows of one (b,h); 8 warps; warp = 16 rows x 64 cols.
// Q fragments hoisted to registers (arithmetic identical to R9).
// ===========================================================================
#define AP 72
#define KVF 4608                 // floats per K (or V) buffer: 64*72
__global__ __launch_bounds__(256) void attn_mma(const float* __restrict__ erk,
                                                const float* __restrict__ erv) {
    extern __shared__ float sm[];
    float* Qs  = sm;            // [128][72]
    float* Ks  = sm + 9216;     // 2 x [64][72]
    float* Vs  = sm + 18432;    // 2 x [64][72]
    float* Ps  = sm + 27648;    // [128][72]
    float* Eks = sm + 36864;    // [9][64]
    float* Evs = sm + 37440;    // [9][64]
    float* qEk = sm + 38016;    // [128][12]

    const int tid = threadIdx.x;
    const int w = tid >> 5, lane = tid & 31;
    const int g = lane >> 2, tig = lane & 3;
    const int rb = w * 16;
    const int i0 = blockIdx.x * 128;
    const int bh = blockIdx.y;
    const int b = bh / H_, h = bh % H_;

    const float* QT = g_qT + (size_t)b * L_ * C_ + h * D_;
    const float* KT = g_kT + (size_t)b * L_ * C_ + h * D_;
    const float* VT = g_vT + (size_t)b * L_ * C_ + h * D_;

    const uint32_t ks_u = smem_u32(Ks);
    const uint32_t vs_u = smem_u32(Vs);
    const int cp_r  = tid >> 4;          // 0..15
    const int cp_d4 = (tid & 15) * 4;

    // Prefetch K/V tile 0 into buffer 0.
#pragma unroll
    for (int it = 0; it < 4; it++) {
        int r = it * 16 + cp_r;
        uint32_t so = (uint32_t)(r * AP + cp_d4) * 4;
        cp_async16(ks_u + so, KT + (size_t)r * C_ + cp_d4);
        cp_async16(vs_u + so, VT + (size_t)r * C_ + cp_d4);
    }
    CP_COMMIT();

    // Stage Q (pre-scaled by 1/8, exact) + embedding tables.
#pragma unroll
    for (int it = 0; it < 8; it++) {
        int idx = it * 256 + tid;
        int r = idx >> 4, d4 = (idx & 15) * 4;
        float4 q4 = *(const float4*)(QT + (size_t)(i0 + r) * C_ + d4);
        Qs[r * AP + d4 + 0] = q4.x * 0.125f;
        Qs[r * AP + d4 + 1] = q4.y * 0.125f;
        Qs[r * AP + d4 + 2] = q4.z * 0.125f;
        Qs[r * AP + d4 + 3] = q4.w * 0.125f;
    }
    for (int e = tid; e < NW_ * 64; e += 256) {
        int dd = e >> 6, r = e & 63;
        Eks[dd * 64 + r] = erk[(h * NW_ + dd) * 64 + r];
        Evs[dd * 64 + r] = erv[(h * NW_ + dd) * 64 + r];
    }
    __syncthreads();

    // qEk[i][dd] = (q_i/8) . Ek[dd]
    for (int e = tid; e < 128 * NW_; e += 256) {
        int dd = e / 128, i = e % 128;
        float s = 0.f;
#pragma unroll
        for (int d = 0; d < 64; d++) s += Qs[i * AP + d] * Eks[dd * 64 + d];
        qEk[i * 12 + dd] = s;
    }

    // Q fragments into registers (reads own warp's rows; no later writes to Qs)
    uint32_t qf[8][4];
#pragma unroll
    for (int ks = 0; ks < 8; ks++) {
        const int k0 = ks * 8;
        qf[ks][0] = __float_as_uint(Qs[(rb + g) * AP + k0 + tig]);
        qf[ks][1] = __float_as_uint(Qs[(rb + g + 8) * AP + k0 + tig]);
        qf[ks][2] = __float_as_uint(Qs[(rb + g) * AP + k0 + tig + 4]);
        qf[ks][3] = __float_as_uint(Qs[(rb + g + 8) * AP + k0 + tig + 4]);
    }

    float m0 = -1e30f, m1 = -1e30f, l0 = 0.f, l1 = 0.f;
    float o[8][4];
#pragma unroll
    for (int nt = 0; nt < 8; nt++)
#pragma unroll
        for (int i = 0; i < 4; i++) o[nt][i] = 0.f;

    const int qi0 = i0 + rb + g;
    const int qi1 = qi0 + 8;
    const int NT = L_ / 64;

    for (int jt = 0; jt < NT; jt++) {
        const int j0 = jt * 64;
        const int cur = jt & 1;
        if (jt + 1 < NT) {
            const float* Kn = KT + (size_t)(j0 + 64) * C_;
            const float* Vn = VT + (size_t)(j0 + 64) * C_;
            uint32_t bo = (uint32_t)((cur ^ 1) * KVF) * 4;
#pragma unroll
            for (int it = 0; it < 4; it++) {
                int r = it * 16 + cp_r;
                uint32_t so = bo + (uint32_t)(r * AP + cp_d4) * 4;
                cp_async16(ks_u + so, Kn + (size_t)r * C_ + cp_d4);
                cp_async16(vs_u + so, Vn + (size_t)r * C_ + cp_d4);
            }
            CP_COMMIT();
            CP_WAIT1();
        } else {
            CP_WAIT0();
        }
        __syncthreads();   // current K/V visible; also fences qEk (jt=0)

        const float* Kc = Ks + cur * KVF;
        const float* Vc = Vs + cur * KVF;

        // S = (Q/8) K^T
        float s[8][4];
#pragma unroll
        for (int nt = 0; nt < 8; nt++)
#pragma unroll
            for (int i = 0; i < 4; i++) s[nt][i] = 0.f;
#pragma unroll
        for (int ks = 0; ks < 8; ks++) {
            const int k0 = ks * 8;
#pragma unroll
            for (int nt = 0; nt < 8; nt++) {
                uint32_t b0 = __float_as_uint(Kc[(nt * 8 + g) * AP + k0 + tig]);
                uint32_t b1 = __float_as_uint(Kc[(nt * 8 + g) * AP + k0 + tig + 4]);
                mma_tf32(s[nt], qf[ks], b0, b1);
            }
        }

        // Relative-K band bias (scale folded into qEk)
        const bool near = (j0 + 63 >= i0 - 4) && (j0 <= i0 + 131);
        if (near) {
#pragma unroll
            for (int nt = 0; nt < 8; nt++) {
#pragma unroll
                for (int c = 0; c < 2; c++) {
                    int j = j0 + nt * 8 + 2 * tig + c;
                    int d0 = j - qi0;
                    if (d0 >= -4 && d0 <= 4) s[nt][c] += qEk[(rb + g) * 12 + d0 + 4];
                    int d1 = j - qi1;
                    if (d1 >= -4 && d1 <= 4) s[nt][c + 2] += qEk[(rb + g + 8) * 12 + d1 + 4];
                }
            }
        }

        // Online softmax (4-lane row reductions)
        float tm0 = -1e30f, tm1 = -1e30f;
#pragma unroll
        for (int nt = 0; nt < 8; nt++) {
            tm0 = fmaxf(tm0, fmaxf(s[nt][0], s[nt][1]));
            tm1 = fmaxf(tm1, fmaxf(s[nt][2], s[nt][3]));
        }
#pragma unroll
        for (int off = 1; off <= 2; off <<= 1) {
            tm0 = fmaxf(tm0, __shfl_xor_sync(0xffffffffu, tm0, off));
            tm1 = fmaxf(tm1, __shfl_xor_sync(0xffffffffu, tm1, off));
        }
        float mn0 = fmaxf(m0, tm0), mn1 = fmaxf(m1, tm1);
        float ts0 = 0.f, ts1 = 0.f;
#pragma unroll
        for (int nt = 0; nt < 8; nt++) {
            s[nt][0] = __expf(s[nt][0] - mn0);
            s[nt][1] = __expf(s[nt][1] - mn0);
            s[nt][2] = __expf(s[nt][2] - mn1);
            s[nt][3] = __expf(s[nt][3] - mn1);
            ts0 += s[nt][0] + s[nt][1];
            ts1 += s[nt][2] + s[nt][3];
        }
#pragma unroll
        for (int off = 1; off <= 2; off <<= 1) {
            ts0 += __shfl_xor_sync(0xffffffffu, ts0, off);
            ts1 += __shfl_xor_sync(0xffffffffu, ts1, off);
        }
        float al0 = __expf(m0 - mn0), al1 = __expf(m1 - mn1);
        l0 = l0 * al0 + ts0;  m0 = mn0;
        l1 = l1 * al1 + ts1;  m1 = mn1;
#pragma unroll
        for (int nt = 0; nt < 8; nt++) {
            o[nt][0] *= al0; o[nt][1] *= al0;
            o[nt][2] *= al1; o[nt][3] *= al1;
        }

        // Stage P (tf32-rounded); rows owned by this warp.
#pragma unroll
        for (int nt = 0; nt < 8; nt++) {
            int col = nt * 8 + 2 * tig;
            *(float2*)&Ps[(rb + g) * AP + col] =
                make_float2(__uint_as_float(f2tf32(s[nt][0])),
                            __uint_as_float(f2tf32(s[nt][1])));
            *(float2*)&Ps[(rb + g + 8) * AP + col] =
                make_float2(__uint_as_float(f2tf32(s[nt][2])),
                            __uint_as_float(f2tf32(s[nt][3])));
        }
        __syncwarp();

        // O += P V
#pragma unroll
        for (int ks = 0; ks < 8; ks++) {
            const int k0 = ks * 8;
            uint32_t a[4];
            a[0] = __float_as_uint(Ps[(rb + g) * AP + k0 + tig]);
            a[1] = __float_as_uint(Ps[(rb + g + 8) * AP + k0 + tig]);
            a[2] = __float_as_uint(Ps[(rb + g) * AP + k0 + tig + 4]);
            a[3] = __float_as_uint(Ps[(rb + g + 8) * AP + k0 + tig + 4]);
#pragma unroll
            for (int nt = 0; nt < 8; nt++) {
                uint32_t b0 = __float_as_uint(Vc[(k0 + tig) * AP + nt * 8 + g]);
                uint32_t b1 = __float_as_uint(Vc[(k0 + tig + 4) * AP + nt * 8 + g]);
                mma_tf32(o[nt], a, b0, b1);
            }
        }

        // Relative-V band
        if (near) {
#pragma unroll
            for (int dd = 0; dd < NW_; dd++) {
                int j0r = qi0 + dd - 4 - j0;
                if (j0r >= 0 && j0r < 64) {
                    float p = Ps[(rb + g) * AP + j0r];
#pragma unroll
                    for (int nt = 0; nt < 8; nt++) {
                        int col = nt * 8 + 2 * tig;
                        o[nt][0] += p * Evs[dd * 64 + col];
                        o[nt][1] += p * Evs[dd * 64 + col + 1];
                    }
                }
                int j1r = qi1 + dd - 4 - j0;
                if (j1r >= 0 && j1r < 64) {
                    float p = Ps[(rb + g + 8) * AP + j1r];
#pragma unroll
                    for (int nt = 0; nt < 8; nt++) {
                        int col = nt * 8 + 2 * tig;
                        o[nt][2] += p * Evs[dd * 64 + col];
                        o[nt][3] += p * Evs[dd * 64 + col + 1];
                    }
                }
            }
        }
        __syncthreads();   // all reads of buf cur done before re-prefetch
    }

    // Epilogue: normalize, tf32-round, store resT[b][l][h*64+dim].
    float inv0 = 1.0f / l0, inv1 = 1.0f / l1;
    float* r0p = g_resT + ((size_t)b * L_ + qi0) * C_ + h * D_;
    float* r1p = g_resT + ((size_t)b * L_ + qi1) * C_ + h * D_;
#pragma unroll
    for (int nt = 0; nt < 8; nt++) {
        int col = nt * 8 + 2 * tig;
        *(float2*)(r0p + col) = make_float2(__uint_as_float(f2tf32(o[nt][0] * inv0)),
                                            __uint_as_float(f2tf32(o[nt][1] * inv0)));
        *(float2*)(r1p + col) = make_float2(__uint_as_float(f2tf32(o[nt][2] * inv1)),
                                            __uint_as_float(f2tf32(o[nt][3] * inv1)));
    }
}

// ---------------------------------------------------------------------------
extern "C" void kernel_launch(void* const* d_in, const int* in_sizes, int n_in,
                              void* d_out, int out_size) {
    const float* x   = (const float*)d_in[0];
    const float* wq  = (const float*)d_in[1];
    const float* bq  = (const float*)d_in[2];
    const float* wk  = (const float*)d_in[3];
    const float* bk  = (const float*)d_in[4];
    const float* wv  = (const float*)d_in[5];
    const float* bv  = (const float*)d_in[6];
    const float* wo  = (const float*)d_in[7];
    const float* bo  = (const float*)d_in[8];
    const float* erk = (const float*)d_in[9];
    const float* erv = (const float*)d_in[10];
    float* out = (float*)d_out;

    float *gqT, *gkT, *gvT, *gxT, *gresT, *gwr;
    cudaGetSymbolAddress((void**)&gqT,   g_qT);
    cudaGetSymbolAddress((void**)&gkT,   g_kT);
    cudaGetSymbolAddress((void**)&gvT,   g_vT);
    cudaGetSymbolAddress((void**)&gxT,   g_xT);
    cudaGetSymbolAddress((void**)&gresT, g_resT);
    cudaGetSymbolAddress((void**)&gwr,   g_wr);

    const int attn_smem = 39552 * 4;    // 158208 bytes
    const int gemm_smem = GEMM_SMEMF * 4;  // 73728 bytes
    cudaFuncSetAttribute(attn_mma, cudaFuncAttributeMaxDynamicSharedMemorySize,
                         attn_smem);
    cudaFuncSetAttribute(qkv_mma, cudaFuncAttributeMaxDynamicSharedMemorySize,
                         gemm_smem);
    cudaFuncSetAttribute(proj_mma, cudaFuncAttributeMaxDynamicSharedMemorySize,
                         gemm_smem);

    // x[b][c][l] -> tf32(xT[b][l][c]); round weights once
    dim3 tgrid(L_ / 32, C_ / 32, B_);
    transpose_kernel<<<tgrid, 256>>>(x, gxT, C_, L_);
    dim3 wgrid(C_ * C_ / 1024, 4);
    round_w<<<wgrid, 256>>>(wq, wk, wv, wo, gwr);

    // Fused QKV, transposed tf32 outputs (cp.async pipelined)
    dim3 qgrid(C_ / 128, L_ / 128, B_ * 3);   // (3, 8, 24)
    qkv_mma<<<qgrid, 256, gemm_smem>>>(gwr, bq, bk, bv, gxT, gqT, gkT, gvT);

    // Tensor-core attention (128 q-rows per block)
    dim3 agrid(L_ / 128, B_ * H_);            // (8, 48)
    attn_mma<<<agrid, 256, attn_smem>>>(erk, erv);

    // O projection (cp.async pipelined)
    dim3 ogrid(L_ / 128, C_ / 128, B_);       // (8, 3, 8)
    proj_mma<<<ogrid, 256, gemm_smem>>>(bo, gresT, out);
}

// round 12
// speedup vs baseline: 1.2403x; 1.0460x over previous
#include <cuda_runtime.h>
#include <cstdint>

#define B_ 8
#define C_ 384
#define L_ 1024
#define H_ 6
#define D_ 64
#define NW_ 9   // 2*window+1

// Scratch (allocation-free rule: device globals). All [b][l][c] layout.
__device__ float g_qT[B_*L_*C_];
__device__ float g_kT[B_*L_*C_];
__device__ float g_vT[B_*L_*C_];
__device__ float g_xT[B_*L_*C_];    // tf32-rounded
__device__ float g_resT[B_*L_*C_];  // tf32-rounded (attn epilogue)
__device__ float g_wr[4*C_*C_];     // tf32-rounded wq,wk,wv,wo

__device__ __forceinline__ uint32_t f2tf32(float f) {
    uint32_t r;
    asm("cvt.rna.tf32.f32 %0, %1;" : "=r"(r) : "f"(f));
    return r;
}

__device__ __forceinline__ void mma_tf32(float* d, const uint32_t* a,
                                         uint32_t b0, uint32_t b1) {
    asm volatile("mma.sync.aligned.m16n8k8.row.col.f32.tf32.tf32.f32 "
                 "{%0,%1,%2,%3}, {%4,%5,%6,%7}, {%8,%9}, {%0,%1,%2,%3};"
                 : "+f"(d[0]), "+f"(d[1]), "+f"(d[2]), "+f"(d[3])
                 : "r"(a[0]), "r"(a[1]), "r"(a[2]), "r"(a[3]),
                   "r"(b0), "r"(b1));
}

__device__ __forceinline__ uint32_t smem_u32(const void* p) {
    uint32_t a;
    asm("{ .reg .u64 t; cvta.to.shared.u64 t, %1; cvt.u32.u64 %0, t; }"
        : "=r"(a) : "l"(p));
    return a;
}
__device__ __forceinline__ void cp_async16(uint32_t s, const void* g) {
    asm volatile("cp.async.cg.shared.global [%0], [%1], 16;" :: "r"(s), "l"(g));
}
#define CP_COMMIT() asm volatile("cp.async.commit_group;" ::: "memory")
#define CP_WAIT1()  asm volatile("cp.async.wait_group 1;" ::: "memory")
#define CP_WAIT0()  asm volatile("cp.async.wait_group 0;" ::: "memory")

// ===========================================================================
// Transpose + tf32 round: dst[b][col][row] = rna_tf32(src[b][row][col]).
// ===========================================================================
__global__ __launch_bounds__(256) void transpose_kernel(const float* __restrict__ src,
                                                        float* __restrict__ dst,
                                                        int rows, int cols) {
    __shared__ float tile[32][33];
    const int b = blockIdx.z;
    const int r0 = blockIdx.y * 32;
    const int c0 = blockIdx.x * 32;
    const int tx = threadIdx.x & 31, ty = threadIdx.x >> 5;
    const float* sb = src + (size_t)b * rows * cols;
    float* db = dst + (size_t)b * rows * cols;
#pragma unroll
    for (int i = 0; i < 4; i++)
        tile[ty + i * 8][tx] = sb[(size_t)(r0 + ty + i * 8) * cols + c0 + tx];
    __syncthreads();
#pragma unroll
    for (int i = 0; i < 4; i++)
        db[(size_t)(c0 + ty + i * 8) * rows + r0 + tx] =
            __uint_as_float(f2tf32(tile[tx][ty + i * 8]));
}

// ===========================================================================
// Round the four weight matrices to tf32 once.
// ===========================================================================
__global__ __launch_bounds__(256) void round_w(const float* __restrict__ w0,
                                               const float* __restrict__ w1,
                                               const float* __restrict__ w2,
                                               const float* __restrict__ w3,
                                               float* __restrict__ dst) {
    const int m = blockIdx.y;
    const float* src = (m == 0) ? w0 : (m == 1) ? w1 : (m == 2) ? w2 : w3;
    int idx = (blockIdx.x * 256 + threadIdx.x) * 4;
    float4 v = *(const float4*)(src + idx);
    uint4 t = make_uint4(f2tf32(v.x), f2tf32(v.y), f2tf32(v.z), f2tf32(v.w));
    *(uint4*)(dst + (size_t)m * C_ * C_ + idx) = t;
}

// ===========================================================================
// cp.async double-buffered tf32 GEMM core (inputs pre-rounded).
// Tile 128x128, K chunks of 32. Smem: 4 buffers of [128][36].
// ===========================================================================
#define GEMM_SMEMF (4 * 128 * 36)   // 73728 bytes

__device__ __forceinline__ void gemm_stage(uint32_t sa, uint32_t sb,
                                           const float* Ag, const float* Bg,
                                           int c0, int tid) {
    const int r_ = tid >> 3;
    const int u  = (tid & 7) * 4;
#pragma unroll
    for (int it = 0; it < 4; it++) {
        int row = it * 32 + r_;
        uint32_t so = (uint32_t)(row * 36 + u) * 4;
        cp_async16(sa + so, Ag + (size_t)row * C_ + c0 + u);
        cp_async16(sb + so, Bg + (size_t)row * C_ + c0 + u);
    }
}

__device__ __forceinline__ void gemm_core(float acc[2][8][4], float* smem,
                                          const float* Ag, const float* Bg,
                                          int tid) {
    const int lane = tid & 31;
    const int g = lane >> 2, tig = lane & 3;
    const int wid = tid >> 5;
    const int warpM = wid & 3, warpN = wid >> 2;
    float* As = smem;
    float* Bs = smem + 2 * 128 * 36;
    const uint32_t as_u = smem_u32(As);
    const uint32_t bs_u = smem_u32(Bs);
    const uint32_t bufb = 128 * 36 * 4;

    gemm_stage(as_u, bs_u, Ag, Bg, 0, tid);
    CP_COMMIT();

    for (int ct = 0; ct < C_ / 32; ct++) {
        const int cur = ct & 1;
        if (ct + 1 < C_ / 32) {
            gemm_stage(as_u + (cur ^ 1) * bufb, bs_u + (cur ^ 1) * bufb,
                       Ag, Bg, (ct + 1) * 32, tid);
            CP_COMMIT();
            CP_WAIT1();
        } else {
            CP_WAIT0();
        }
        __syncthreads();
        const float* Ac = As + cur * 128 * 36;
        const float* Bc = Bs + cur * 128 * 36;
#pragma unroll
        for (int ks = 0; ks < 4; ks++) {
            const int k0 = ks * 8;
            uint32_t a[2][4];
#pragma unroll
            for (int mt = 0; mt < 2; mt++) {
                int rb = warpM * 32 + mt * 16;
                a[mt][0] = __float_as_uint(Ac[(rb + g) * 36 + k0 + tig]);
                a[mt][1] = __float_as_uint(Ac[(rb + g + 8) * 36 + k0 + tig]);
                a[mt][2] = __float_as_uint(Ac[(rb + g) * 36 + k0 + tig + 4]);
                a[mt][3] = __float_as_uint(Ac[(rb + g + 8) * 36 + k0 + tig + 4]);
            }
#pragma unroll
            for (int nt = 0; nt < 8; nt++) {
                int nb = warpN * 64 + nt * 8;
                uint32_t b0 = __float_as_uint(Bc[(nb + g) * 36 + k0 + tig]);
                uint32_t b1 = __float_as_uint(Bc[(nb + g) * 36 + k0 + tig + 4]);
#pragma unroll
                for (int mt = 0; mt < 2; mt++)
                    mma_tf32(acc[mt][nt], a[mt], b0, b1);
            }
        }
        __syncthreads();
    }
}

// ===========================================================================
// Fused QKV projection, TRANSPOSED tf32 output.
// ===========================================================================
__global__ __launch_bounds__(256) void qkv_mma(const float* __restrict__ Wr,
                                               const float* __restrict__ bq,
                                               const float* __restrict__ bk,
                                               const float* __restrict__ bv,
                                               const float* __restrict__ XT,
                                               float* __restrict__ q,
                                               float* __restrict__ k,
                                               float* __restrict__ v) {
    extern __shared__ float smem[];
    const int tid = threadIdx.x;
    const int lane = tid & 31;
    const int g = lane >> 2, tig = lane & 3;
    const int wid = tid >> 5;
    const int warpM = wid & 3, warpN = wid >> 2;
    const int pid = blockIdx.z % 3;
    const int b   = blockIdx.z / 3;
    const int l0  = blockIdx.y * 128;
    const int o0  = blockIdx.x * 128;

    const float* bias = (pid == 0) ? bq : (pid == 1) ? bk : bv;
    float* Y          = (pid == 0) ? q  : (pid == 1) ? k  : v;
    const float* Ag = XT + ((size_t)b * L_ + l0) * C_;
    const float* Bg = g_wr + (size_t)pid * C_ * C_ + (size_t)o0 * C_;

    float acc[2][8][4];
#pragma unroll
    for (int mt = 0; mt < 2; mt++)
#pragma unroll
        for (int nt = 0; nt < 8; nt++)
#pragma unroll
            for (int i = 0; i < 4; i++) acc[mt][nt][i] = 0.f;

    gemm_core(acc, smem, Ag, Bg, tid);

#pragma unroll
    for (int mt = 0; mt < 2; mt++) {
        int lr0 = l0 + warpM * 32 + mt * 16;
        float* y0 = Y + ((size_t)b * L_ + lr0 + g) * C_;
        float* y1 = Y + ((size_t)b * L_ + lr0 + g + 8) * C_;
#pragma unroll
        for (int nt = 0; nt < 8; nt++) {
            int col = o0 + warpN * 64 + nt * 8 + 2 * tig;
            float bv0 = bias[col], bv1 = bias[col + 1];
            *(float2*)(y0 + col) = make_float2(__uint_as_float(f2tf32(acc[mt][nt][0] + bv0)),
                                               __uint_as_float(f2tf32(acc[mt][nt][1] + bv1)));
            *(float2*)(y1 + col) = make_float2(__uint_as_float(f2tf32(acc[mt][nt][2] + bv0)),
                                               __uint_as_float(f2tf32(acc[mt][nt][3] + bv1)));
        }
    }
}

// ===========================================================================
// O projection: out[b][o][l] = sum_c W[o][c] * resT[b][l][c] + bias[o]
// ===========================================================================
__global__ __launch_bounds__(256) void proj_mma(const float* __restrict__ bias,
                                                const float* __restrict__ XT,
                                                float* __restrict__ Y) {
    extern __shared__ float smem[];
    const int tid = threadIdx.x;
    const int lane = tid & 31;
    const int g = lane >> 2, tig = lane & 3;
    const int wid = tid >> 5;
    const int warpM = wid & 3, warpN = wid >> 2;
    const int b  = blockIdx.z;
    const int o0 = blockIdx.y * 128;
    const int l0 = blockIdx.x * 128;

    const float* Ag = g_wr + (size_t)3 * C_ * C_ + (size_t)o0 * C_;
    const float* Bg = XT + ((size_t)b * L_ + l0) * C_;

    float acc[2][8][4];
#pragma unroll
    for (int mt = 0; mt < 2; mt++)
#pragma unroll
        for (int nt = 0; nt < 8; nt++)
#pragma unroll
            for (int i = 0; i < 4; i++) acc[mt][nt][i] = 0.f;

    gemm_core(acc, smem, Ag, Bg, tid);

#pragma unroll
    for (int mt = 0; mt < 2; mt++) {
        int r0 = o0 + warpM * 32 + mt * 16;
        float bv0 = bias[r0 + g];
        float bv1 = bias[r0 + g + 8];
        float* y0 = Y + ((size_t)b * C_ + r0 + g) * L_;
        float* y1 = Y + ((size_t)b * C_ + r0 + g + 8) * L_;
#pragma unroll
        for (int nt = 0; nt < 8; nt++) {
            int col = l0 + warpN * 64 + nt * 8 + 2 * tig;
            *(float2*)(y0 + col) = make_float2(acc[mt][nt][0] + bv0, acc[mt][nt][1] + bv0);
            *(float2*)(y1 + col) = make_float2(acc[mt][nt][2] + bv1, acc[mt][nt][3] + bv1);
        }
    }
}

// ===========================================================================
// Tensor-core flash attention, cp.async double-buffered K/V, 2 CTAs/SM.
// Block: 128 q-rows of one (b,h); 8 warps; warp = 16 rows x 64 cols.
// Q-stage buffer is reused as P after Q fragments are hoisted to registers
// (qEk + hoist complete before the jt=0 __syncthreads; P rows warp-private).
// Arithmetic identical to R11. Smem 113,664 B -> 2 CTAs/SM.
// ===========================================================================
#define AP 68
#define KVF 4352                 // floats per K (or V) buffer: 64*68
#define SM_QP  0                 // Q-stage then P: [128][68] = 8704
#define SM_K   8704              // 2 x [64][68]   = 8704
#define SM_V   17408             // 2 x [64][68]   = 8704
#define SM_EK  26112             // [9][64] = 576
#define SM_EV  26688             // [9][64] = 576
#define SM_QEK 27264             // [128][9] = 1152
#define ATTN_SMEMF 28416         // 113664 bytes

__global__ __launch_bounds__(256, 2) void attn_mma(const float* __restrict__ erk,
                                                   const float* __restrict__ erv) {
    extern __shared__ float sm[];
    float* QP  = sm + SM_QP;
    float* Ks  = sm + SM_K;
    float* Vs  = sm + SM_V;
    float* Eks = sm + SM_EK;
    float* Evs = sm + SM_EV;
    float* qEk = sm + SM_QEK;

    const int tid = threadIdx.x;
    const int w = tid >> 5, lane = tid & 31;
    const int g = lane >> 2, tig = lane & 3;
    const int rb = w * 16;
    const int i0 = blockIdx.x * 128;
    const int bh = blockIdx.y;
    const int b = bh / H_, h = bh % H_;

    const float* QT = g_qT + (size_t)b * L_ * C_ + h * D_;
    const float* KT = g_kT + (size_t)b * L_ * C_ + h * D_;
    const float* VT = g_vT + (size_t)b * L_ * C_ + h * D_;

    const uint32_t ks_u = smem_u32(Ks);
    const uint32_t vs_u = smem_u32(Vs);
    const int cp_r  = tid >> 4;          // 0..15
    const int cp_d4 = (tid & 15) * 4;

    // Prefetch K/V tile 0 into buffer 0.
#pragma unroll
    for (int it = 0; it < 4; it++) {
        int r = it * 16 + cp_r;
        uint32_t so = (uint32_t)(r * AP + cp_d4) * 4;
        cp_async16(ks_u + so, KT + (size_t)r * C_ + cp_d4);
        cp_async16(vs_u + so, VT + (size_t)r * C_ + cp_d4);
    }
    CP_COMMIT();

    // Stage Q (pre-scaled by 1/8, exact) + embedding tables.
#pragma unroll
    for (int it = 0; it < 8; it++) {
        int idx = it * 256 + tid;
        int r = idx >> 4, d4 = (idx & 15) * 4;
        float4 q4 = *(const float4*)(QT + (size_t)(i0 + r) * C_ + d4);
        QP[r * AP + d4 + 0] = q4.x * 0.125f;
        QP[r * AP + d4 + 1] = q4.y * 0.125f;
        QP[r * AP + d4 + 2] = q4.z * 0.125f;
        QP[r * AP + d4 + 3] = q4.w * 0.125f;
    }
    for (int e = tid; e < NW_ * 64; e += 256) {
        int dd = e >> 6, r = e & 63;
        Eks[dd * 64 + r] = erk[(h * NW_ + dd) * 64 + r];
        Evs[dd * 64 + r] = erv[(h * NW_ + dd) * 64 + r];
    }
    __syncthreads();

    // qEk[i][dd] = (q_i/8) . Ek[dd]
    for (int e = tid; e < 128 * NW_; e += 256) {
        int dd = e / 128, i = e % 128;
        float s = 0.f;
#pragma unroll
        for (int d = 0; d < 64; d++) s += QP[i * AP + d] * Eks[dd * 64 + d];
        qEk[i * NW_ + dd] = s;
    }

    // Q fragments into registers.
    uint32_t qf[8][4];
#pragma unroll
    for (int ks = 0; ks < 8; ks++) {
        const int k0 = ks * 8;
        qf[ks][0] = __float_as_uint(QP[(rb + g) * AP + k0 + tig]);
        qf[ks][1] = __float_as_uint(QP[(rb + g + 8) * AP + k0 + tig]);
        qf[ks][2] = __float_as_uint(QP[(rb + g) * AP + k0 + tig + 4]);
        qf[ks][3] = __float_as_uint(QP[(rb + g + 8) * AP + k0 + tig + 4]);
    }

    float m0 = -1e30f, m1 = -1e30f, l0 = 0.f, l1 = 0.f;
    float o[8][4];
#pragma unroll
    for (int nt = 0; nt < 8; nt++)
#pragma unroll
        for (int i = 0; i < 4; i++) o[nt][i] = 0.f;

    const int qi0 = i0 + rb + g;
    const int qi1 = qi0 + 8;
    const int NT = L_ / 64;

    for (int jt = 0; jt < NT; jt++) {
        const int j0 = jt * 64;
        const int cur = jt & 1;
        if (jt + 1 < NT) {
            const float* Kn = KT + (size_t)(j0 + 64) * C_;
            const float* Vn = VT + (size_t)(j0 + 64) * C_;
            uint32_t bo = (uint32_t)((cur ^ 1) * KVF) * 4;
#pragma unroll
            for (int it = 0; it < 4; it++) {
                int r = it * 16 + cp_r;
                uint32_t so = bo + (uint32_t)(r * AP + cp_d4) * 4;
                cp_async16(ks_u + so, Kn + (size_t)r * C_ + cp_d4);
                cp_async16(vs_u + so, Vn + (size_t)r * C_ + cp_d4);
            }
            CP_COMMIT();
            CP_WAIT1();
        } else {
            CP_WAIT0();
        }
        __syncthreads();   // K/V visible; qEk + Q-frag hoist fenced (jt=0);
                           // prev tile's P/K/V reads complete.

        const float* Kc = Ks + cur * KVF;
        const float* Vc = Vs + cur * KVF;

        // S = (Q/8) K^T
        float s[8][4];
#pragma unroll
        for (int nt = 0; nt < 8; nt++)
#pragma unroll
            for (int i = 0; i < 4; i++) s[nt][i] = 0.f;
#pragma unroll
        for (int ks = 0; ks < 8; ks++) {
            const int k0 = ks * 8;
#pragma unroll
            for (int nt = 0; nt < 8; nt++) {
                uint32_t b0 = __float_as_uint(Kc[(nt * 8 + g) * AP + k0 + tig]);
                uint32_t b1 = __float_as_uint(Kc[(nt * 8 + g) * AP + k0 + tig + 4]);
                mma_tf32(s[nt], qf[ks], b0, b1);
            }
        }

        // Relative-K band bias (scale folded into qEk)
        const bool near = (j0 + 63 >= i0 - 4) && (j0 <= i0 + 131);
        if (near) {
#pragma unroll
            for (int nt = 0; nt < 8; nt++) {
#pragma unroll
                for (int c = 0; c < 2; c++) {
                    int j = j0 + nt * 8 + 2 * tig + c;
                    int d0 = j - qi0;
                    if (d0 >= -4 && d0 <= 4) s[nt][c] += qEk[(rb + g) * NW_ + d0 + 4];
                    int d1 = j - qi1;
                    if (d1 >= -4 && d1 <= 4) s[nt][c + 2] += qEk[(rb + g + 8) * NW_ + d1 + 4];
                }
            }
        }

        // Online softmax (4-lane row reductions)
        float tm0 = -1e30f, tm1 = -1e30f;
#pragma unroll
        for (int nt = 0; nt < 8; nt++) {
            tm0 = fmaxf(tm0, fmaxf(s[nt][0], s[nt][1]));
            tm1 = fmaxf(tm1, fmaxf(s[nt][2], s[nt][3]));
        }
#pragma unroll
        for (int off = 1; off <= 2; off <<= 1) {
            tm0 = fmaxf(tm0, __shfl_xor_sync(0xffffffffu, tm0, off));
            tm1 = fmaxf(tm1, __shfl_xor_sync(0xffffffffu, tm1, off));
        }
        float mn0 = fmaxf(m0, tm0), mn1 = fmaxf(m1, tm1);
        float ts0 = 0.f, ts1 = 0.f;
#pragma unroll
        for (int nt = 0; nt < 8; nt++) {
            s[nt][0] = __expf(s[nt][0] - mn0);
            s[nt][1] = __expf(s[nt][1] - mn0);
            s[nt][2] = __expf(s[nt][2] - mn1);
            s[nt][3] = __expf(s[nt][3] - mn1);
            ts0 += s[nt][0] + s[nt][1];
            ts1 += s[nt][2] + s[nt][3];
        }
#pragma unroll
        for (int off = 1; off <= 2; off <<= 1) {
            ts0 += __shfl_xor_sync(0xffffffffu, ts0, off);
            ts1 += __shfl_xor_sync(0xffffffffu, ts1, off);
        }
        float al0 = __expf(m0 - mn0), al1 = __expf(m1 - mn1);
        l0 = l0 * al0 + ts0;  m0 = mn0;
        l1 = l1 * al1 + ts1;  m1 = mn1;
#pragma unroll
        for (int nt = 0; nt < 8; nt++) {
            o[nt][0] *= al0; o[nt][1] *= al0;
            o[nt][2] *= al1; o[nt][3] *= al1;
        }

        // Stage P (tf32-rounded) into warp-private rows of QP.
#pragma unroll
        for (int nt = 0; nt < 8; nt++) {
            int col = nt * 8 + 2 * tig;
            *(float2*)&QP[(rb + g) * AP + col] =
                make_float2(__uint_as_float(f2tf32(s[nt][0])),
                            __uint_as_float(f2tf32(s[nt][1])));
            *(float2*)&QP[(rb + g + 8) * AP + col] =
                make_float2(__uint_as_float(f2tf32(s[nt][2])),
                            __uint_as_float(f2tf32(s[nt][3])));
        }
        __syncwarp();

        // O += P V
#pragma unroll
        for (int ks = 0; ks < 8; ks++) {
            const int k0 = ks * 8;
            uint32_t a[4];
            a[0] = __float_as_uint(QP[(rb + g) * AP + k0 + tig]);
            a[1] = __float_as_uint(QP[(rb + g + 8) * AP + k0 + tig]);
            a[2] = __float_as_uint(QP[(rb + g) * AP + k0 + tig + 4]);
            a[3] = __float_as_uint(QP[(rb + g + 8) * AP + k0 + tig + 4]);
#pragma unroll
            for (int nt = 0; nt < 8; nt++) {
                uint32_t b0 = __float_as_uint(Vc[(k0 + tig) * AP + nt * 8 + g]);
                uint32_t b1 = __float_as_uint(Vc[(k0 + tig + 4) * AP + nt * 8 + g]);
                mma_tf32(o[nt], a, b0, b1);
            }
        }

        // Relative-V band
        if (near) {
#pragma unroll
            for (int dd = 0; dd < NW_; dd++) {
                int j0r = qi0 + dd - 4 - j0;
                if (j0r >= 0 && j0r < 64) {
                    float p = QP[(rb + g) * AP + j0r];
#pragma unroll
                    for (int nt = 0; nt < 8; nt++) {
                        int col = nt * 8 + 2 * tig;
                        o[nt][0] += p * Evs[dd * 64 + col];
                        o[nt][1] += p * Evs[dd * 64 + col + 1];
                    }
                }
                int j1r = qi1 + dd - 4 - j0;
                if (j1r >= 0 && j1r < 64) {
                    float p = QP[(rb + g + 8) * AP + j1r];
#pragma unroll
                    for (int nt = 0; nt < 8; nt++) {
                        int col = nt * 8 + 2 * tig;
                        o[nt][2] += p * Evs[dd * 64 + col];
                        o[nt][3] += p * Evs[dd * 64 + col + 1];
                    }
                }
            }
        }
        __syncthreads();   // all reads of buf cur done before re-prefetch
    }

    // Epilogue: normalize, tf32-round, store resT[b][l][h*64+dim].
    float inv0 = 1.0f / l0, inv1 = 1.0f / l1;
    float* r0p = g_resT + ((size_t)b * L_ + qi0) * C_ + h * D_;
    float* r1p = g_resT + ((size_t)b * L_ + qi1) * C_ + h * D_;
#pragma unroll
    for (int nt = 0; nt < 8; nt++) {
        int col = nt * 8 + 2 * tig;
        *(float2*)(r0p + col) = make_float2(__uint_as_float(f2tf32(o[nt][0] * inv0)),
                                            __uint_as_float(f2tf32(o[nt][1] * inv0)));
        *(float2*)(r1p + col) = make_float2(__uint_as_float(f2tf32(o[nt][2] * inv1)),
                                            __uint_as_float(f2tf32(o[nt][3] * inv1)));
    }
}

// ---------------------------------------------------------------------------
extern "C" void kernel_launch(void* const* d_in, const int* in_sizes, int n_in,
                              void* d_out, int out_size) {
    const float* x   = (const float*)d_in[0];
    const float* wq  = (const float*)d_in[1];
    const float* bq  = (const float*)d_in[2];
    const float* wk  = (const float*)d_in[3];
    const float* bk  = (const float*)d_in[4];
    const float* wv  = (const float*)d_in[5];
    const float* bv  = (const float*)d_in[6];
    const float* wo  = (const float*)d_in[7];
    const float* bo  = (const float*)d_in[8];
    const float* erk = (const float*)d_in[9];
    const float* erv = (const float*)d_in[10];
    float* out = (float*)d_out;

    float *gqT, *gkT, *gvT, *gxT, *gresT, *gwr;
    cudaGetSymbolAddress((void**)&gqT,   g_qT);
    cudaGetSymbolAddress((void**)&gkT,   g_kT);
    cudaGetSymbolAddress((void**)&gvT,   g_vT);
    cudaGetSymbolAddress((void**)&gxT,   g_xT);
    cudaGetSymbolAddress((void**)&gresT, g_resT);
    cudaGetSymbolAddress((void**)&gwr,   g_wr);

    const int attn_smem = ATTN_SMEMF * 4;  // 113664 bytes -> 2 CTAs/SM
    const int gemm_smem = GEMM_SMEMF * 4;  // 73728 bytes
    cudaFuncSetAttribute(attn_mma, cudaFuncAttributeMaxDynamicSharedMemorySize,
                         attn_smem);
    cudaFuncSetAttribute(qkv_mma, cudaFuncAttributeMaxDynamicSharedMemorySize,
                         gemm_smem);
    cudaFuncSetAttribute(proj_mma, cudaFuncAttributeMaxDynamicSharedMemorySize,
                         gemm_smem);

    // x[b][c][l] -> tf32(xT[b][l][c]); round weights once
    dim3 tgrid(L_ / 32, C_ / 32, B_);
    transpose_kernel<<<tgrid, 256>>>(x, gxT, C_, L_);
    dim3 wgrid(C_ * C_ / 1024, 4);
    round_w<<<wgrid, 256>>>(wq, wk, wv, wo, gwr);

    // Fused QKV, transposed tf32 outputs (cp.async pipelined)
    dim3 qgrid(C_ / 128, L_ / 128, B_ * 3);   // (3, 8, 24)
    qkv_mma<<<qgrid, 256, gemm_smem>>>(gwr, bq, bk, bv, gxT, gqT, gkT, gvT);

    // Tensor-core attention (128 q-rows per block, 2 CTAs/SM)
    dim3 agrid(L_ / 128, B_ * H_);            // (8, 48)
    attn_mma<<<agrid, 256, attn_smem>>>(erk, erv);

    // O projection (cp.async pipelined)
    dim3 ogrid(L_ / 128, C_ / 128, B_);       // (8, 3, 8)
    proj_mma<<<ogrid, 256, gemm_smem>>>(bo, gresT, out);
}